// round 1
// baseline (speedup 1.0000x reference)
#include <cuda_runtime.h>
#include <cuda_bf16.h>
#include <math.h>

// ---------------------------------------------------------------------------
// Problem constants
// ---------------------------------------------------------------------------
#define EMBED 1024
#define HEADS 16
#define HDIM  64
#define NB    4
#define SEQ   8192
#define TOKENS (NB * SEQ)          // 32768

// Scratch (alloc-free rule: __device__ globals)
__device__ float g_qkv[(size_t)TOKENS * 3 * EMBED];   // [token][{Q,K,V} x 1024]
__device__ float g_mid[(size_t)TOKENS * EMBED];       // gathered attention output M

// ---------------------------------------------------------------------------
// GEMM: C[m,n] = sum_k A[m,k] * B[n,k] + bias[n]
// A: M x K row-major (lda = K), B: N x K row-major (ldb = K), C: ldc stride.
// 128x128 tile, BK=16, 256 threads, 8x8 per thread.
// ---------------------------------------------------------------------------
#define BM 128
#define BN 128
#define BK 16

__global__ void __launch_bounds__(256)
gemm_nt_bias(const float* __restrict__ A, const float* __restrict__ B,
             const float* __restrict__ bias, float* __restrict__ C,
             int K, int ldc)
{
    __shared__ float As[BK][BM + 4];
    __shared__ float Bs[BK][BN + 4];

    const int tid = threadIdx.x;
    const int tx  = tid & 15;          // 0..15 -> N
    const int ty  = tid >> 4;          // 0..15 -> M
    const int row0 = blockIdx.y * BM;
    const int col0 = blockIdx.x * BN;

    float acc[8][8];
#pragma unroll
    for (int i = 0; i < 8; i++)
#pragma unroll
        for (int j = 0; j < 8; j++) acc[i][j] = 0.0f;

    for (int kt = 0; kt < K; kt += BK) {
        // Load A tile (128x16) and B tile (128x16) as float4, store K-major.
#pragma unroll
        for (int r = 0; r < 2; r++) {
            int f    = tid + r * 256;      // 0..511 float4 id
            int arow = f >> 2;             // 0..127
            int ak   = (f & 3) << 2;       // 0,4,8,12
            float4 va = *(const float4*)&A[(size_t)(row0 + arow) * K + kt + ak];
            As[ak + 0][arow] = va.x; As[ak + 1][arow] = va.y;
            As[ak + 2][arow] = va.z; As[ak + 3][arow] = va.w;
            float4 vb = *(const float4*)&B[(size_t)(col0 + arow) * K + kt + ak];
            Bs[ak + 0][arow] = vb.x; Bs[ak + 1][arow] = vb.y;
            Bs[ak + 2][arow] = vb.z; Bs[ak + 3][arow] = vb.w;
        }
        __syncthreads();

#pragma unroll
        for (int k = 0; k < BK; k++) {
            float a[8], b[8];
            *(float4*)&a[0] = *(const float4*)&As[k][ty * 8];
            *(float4*)&a[4] = *(const float4*)&As[k][ty * 8 + 4];
            *(float4*)&b[0] = *(const float4*)&Bs[k][tx * 8];
            *(float4*)&b[4] = *(const float4*)&Bs[k][tx * 8 + 4];
#pragma unroll
            for (int i = 0; i < 8; i++)
#pragma unroll
                for (int j = 0; j < 8; j++)
                    acc[i][j] += a[i] * b[j];
        }
        __syncthreads();
    }

    // Epilogue: add bias, store
#pragma unroll
    for (int i = 0; i < 8; i++) {
        int r = row0 + ty * 8 + i;
#pragma unroll
        for (int j = 0; j < 8; j += 4) {
            int c = col0 + tx * 8 + j;
            float4 o;
            o.x = acc[i][j + 0] + bias[c + 0];
            o.y = acc[i][j + 1] + bias[c + 1];
            o.z = acc[i][j + 2] + bias[c + 2];
            o.w = acc[i][j + 3] + bias[c + 3];
            *(float4*)&C[(size_t)r * ldc + c] = o;
        }
    }
}

// ---------------------------------------------------------------------------
// Per-token "attention": for token (n,s)
//   e[i][j]  = sum_d Q[i,d]*K[j,d] / 32        (16x16 over heads)
//   a        = softmax_j(e)
//   O[i][d]  = sum_l a[i,l] * V[l,d]           (16x64)
// scatter: M[n*8192 + i*512 + s/16, (s%16)*64 + d] = O[i][d]
// One block (256 threads) per token.
// ---------------------------------------------------------------------------
__global__ void __launch_bounds__(256)
attn_kernel(const float* __restrict__ QKV, float* __restrict__ Mout)
{
    const int token = blockIdx.x;
    const int n = token >> 13;           // /8192
    const int s = token & 8191;
    const float* base = QKV + (size_t)token * (3 * EMBED);

    __shared__ float qs[16 * 64];        // Q[i][d]
    __shared__ float ks[64 * 17];        // K transposed: kT[d][j] (padded)
    __shared__ float vs[16 * 64];        // V[l][d]
    __shared__ float es[16 * 16];        // attention

    const int tid = threadIdx.x;

    // Load Q, V contiguous; K with transpose (256 float4 each, 1/thread)
    {
        float4 fq = ((const float4*)base)[tid];
        ((float4*)qs)[tid] = fq;
        float4 fv = ((const float4*)(base + 2 * EMBED))[tid];
        ((float4*)vs)[tid] = fv;
        float4 fk = ((const float4*)(base + EMBED))[tid];
        int j  = tid >> 4;               // head 0..15
        int d0 = (tid & 15) << 2;        // dim 0..60
        ks[(d0 + 0) * 17 + j] = fk.x;
        ks[(d0 + 1) * 17 + j] = fk.y;
        ks[(d0 + 2) * 17 + j] = fk.z;
        ks[(d0 + 3) * 17 + j] = fk.w;
    }
    __syncthreads();

    // Energy + softmax: thread (i,j), i = tid/16, j = tid%16
    {
        const int i = tid >> 4, j = tid & 15;
        float sum = 0.0f;
#pragma unroll
        for (int d = 0; d < 64; d++)
            sum += qs[i * 64 + d] * ks[d * 17 + j];
        float val = sum * 0.03125f;      // 1/sqrt(1024)

        float mx = val;
#pragma unroll
        for (int off = 8; off > 0; off >>= 1)
            mx = fmaxf(mx, __shfl_xor_sync(0xffffffffu, mx, off, 16));
        float p = expf(val - mx);
        float z = p;
#pragma unroll
        for (int off = 8; off > 0; off >>= 1)
            z += __shfl_xor_sync(0xffffffffu, z, off, 16);
        es[i * 16 + j] = p / z;
    }
    __syncthreads();

    // O = attn @ V, scattered store. Thread computes 4 contiguous d.
    {
        const int i  = tid >> 4;         // head row 0..15
        const int d0 = (tid & 15) << 2;  // 0..60
        float4 o = make_float4(0.f, 0.f, 0.f, 0.f);
#pragma unroll
        for (int l = 0; l < 16; l++) {
            float a = es[i * 16 + l];
            float4 v = *(const float4*)&vs[l * 64 + d0];
            o.x += a * v.x; o.y += a * v.y; o.z += a * v.z; o.w += a * v.w;
        }
        const int row = n * SEQ + i * 512 + (s >> 4);
        const int col = (s & 15) * HDIM + d0;
        *(float4*)&Mout[(size_t)row * EMBED + col] = o;
    }
}

// ---------------------------------------------------------------------------
// Launch
// ---------------------------------------------------------------------------
extern "C" void kernel_launch(void* const* d_in, const int* in_sizes, int n_in,
                              void* d_out, int out_size)
{
    const float* x  = (const float*)d_in[0];
    const float* Wq = (const float*)d_in[1];
    const float* Wk = (const float*)d_in[2];
    const float* Wv = (const float*)d_in[3];
    const float* Wo = (const float*)d_in[4];
    const float* bq = (const float*)d_in[5];
    const float* bk = (const float*)d_in[6];
    const float* bv = (const float*)d_in[7];
    const float* bo = (const float*)d_in[8];
    float* out = (float*)d_out;

    float* qkv = nullptr;
    float* mid = nullptr;
    cudaGetSymbolAddress((void**)&qkv, g_qkv);
    cudaGetSymbolAddress((void**)&mid, g_mid);

    dim3 block(256);
    dim3 gridP(EMBED / BN, TOKENS / BM);   // (8, 256)

    // Q/K/V projections into g_qkv (ldc = 3072, column slices)
    gemm_nt_bias<<<gridP, block>>>(x, Wq, bq, qkv + 0 * EMBED, EMBED, 3 * EMBED);
    gemm_nt_bias<<<gridP, block>>>(x, Wk, bk, qkv + 1 * EMBED, EMBED, 3 * EMBED);
    gemm_nt_bias<<<gridP, block>>>(x, Wv, bv, qkv + 2 * EMBED, EMBED, 3 * EMBED);

    // Per-token head-mixing attention + gather into g_mid
    attn_kernel<<<TOKENS, block>>>(qkv, mid);

    // Output projection: out = M @ Wo^T + bo
    gemm_nt_bias<<<gridP, block>>>(mid, Wo, bo, out, EMBED, EMBED);
}

// round 10
// speedup vs baseline: 2.3890x; 2.3890x over previous
#include <cuda_runtime.h>
#include <cuda_bf16.h>
#include <stdint.h>
#include <math.h>

// ---------------------------------------------------------------------------
// Problem constants
// ---------------------------------------------------------------------------
#define EMBED 1024
#define K3    3072           // tripled K for 3xBF16 split GEMM
#define NB    4
#define SEQ   8192
#define TOKENS (NB * SEQ)    // 32768
#define HDIM  64

// ---------------------------------------------------------------------------
// Scratch (__device__ globals; alloc-free rule)
// ---------------------------------------------------------------------------
__device__ __nv_bfloat16 g_x3[(size_t)TOKENS * K3];    // x split  [hi|hi|lo]
__device__ __nv_bfloat16 g_w3qkv[(size_t)3072 * K3];   // Wq/Wk/Wv [hi|lo|hi]
__device__ __nv_bfloat16 g_w3o[(size_t)1024 * K3];     // Wo       [hi|lo|hi]
__device__ float         g_bqkv[3072];                 // concat(bq,bk,bv)
__device__ float         g_qkv[(size_t)TOKENS * 3072]; // fp32 Q|K|V per token
__device__ __nv_bfloat16 g_mid3[(size_t)TOKENS * K3];  // attn out [hi|hi|lo]

// ---------------------------------------------------------------------------
// Helpers
// ---------------------------------------------------------------------------
__device__ __forceinline__ unsigned short bfraw(__nv_bfloat16 h) {
    return *reinterpret_cast<unsigned short*>(&h);
}
__device__ __forceinline__ void split2(float v, unsigned short& h, unsigned short& l) {
    __nv_bfloat16 hb = __float2bfloat16(v);
    __nv_bfloat16 lb = __float2bfloat16(v - __bfloat162float(hb));
    h = bfraw(hb); l = bfraw(lb);
}
__device__ __forceinline__ uint32_t s2u(const void* p) {
    uint32_t a;
    asm("{ .reg .u64 t; cvta.to.shared.u64 t, %1; cvt.u32.u64 %0, t; }" : "=r"(a) : "l"(p));
    return a;
}
__device__ __forceinline__ uint32_t swz(uint32_t o) { return o ^ ((o >> 3) & 0x70); }

__device__ __forceinline__ void ldsm4(uint32_t* r, uint32_t addr) {
    asm volatile("ldmatrix.sync.aligned.m8n8.x4.shared.b16 {%0,%1,%2,%3}, [%4];"
                 : "=r"(r[0]), "=r"(r[1]), "=r"(r[2]), "=r"(r[3]) : "r"(addr));
}
__device__ __forceinline__ void mma16816(float* d, const uint32_t* a,
                                         uint32_t b0, uint32_t b1) {
    asm volatile(
        "mma.sync.aligned.m16n8k16.row.col.f32.bf16.bf16.f32 "
        "{%0,%1,%2,%3}, {%4,%5,%6,%7}, {%8,%9}, {%0,%1,%2,%3};"
        : "+f"(d[0]), "+f"(d[1]), "+f"(d[2]), "+f"(d[3])
        : "r"(a[0]), "r"(a[1]), "r"(a[2]), "r"(a[3]), "r"(b0), "r"(b1));
}

// ---------------------------------------------------------------------------
// Conversion kernels
// ---------------------------------------------------------------------------
__global__ void __launch_bounds__(256)
convA(const float* __restrict__ X, __nv_bfloat16* __restrict__ O) {
    int r = blockIdx.x;
    int c = threadIdx.x * 4;
    float4 v = *(const float4*)&X[(size_t)r * EMBED + c];
    unsigned short h[4], l[4];
    split2(v.x, h[0], l[0]); split2(v.y, h[1], l[1]);
    split2(v.z, h[2], l[2]); split2(v.w, h[3], l[3]);
    ushort4 hh = make_ushort4(h[0], h[1], h[2], h[3]);
    ushort4 ll = make_ushort4(l[0], l[1], l[2], l[3]);
    __nv_bfloat16* row = O + (size_t)r * K3;
    *(ushort4*)&row[c]        = hh;   // A layout: [hi|hi|lo]
    *(ushort4*)&row[1024 + c] = hh;
    *(ushort4*)&row[2048 + c] = ll;
}

__global__ void __launch_bounds__(256)
convW(const float* __restrict__ Wq, const float* __restrict__ Wk,
      const float* __restrict__ Wv, const float* __restrict__ Wo,
      __nv_bfloat16* __restrict__ wqkv, __nv_bfloat16* __restrict__ wo) {
    int r = blockIdx.x;              // 0..4095
    int c = threadIdx.x * 4;
    const float* src = (r < 1024) ? Wq : (r < 2048) ? Wk : (r < 3072) ? Wv : Wo;
    int sr = r & 1023;
    float4 v = *(const float4*)&src[(size_t)sr * EMBED + c];
    unsigned short h[4], l[4];
    split2(v.x, h[0], l[0]); split2(v.y, h[1], l[1]);
    split2(v.z, h[2], l[2]); split2(v.w, h[3], l[3]);
    ushort4 hh = make_ushort4(h[0], h[1], h[2], h[3]);
    ushort4 ll = make_ushort4(l[0], l[1], l[2], l[3]);
    __nv_bfloat16* row = (r < 3072) ? (wqkv + (size_t)r * K3)
                                    : (wo + (size_t)(r - 3072) * K3);
    *(ushort4*)&row[c]        = hh;   // B layout: [hi|lo|hi]
    *(ushort4*)&row[1024 + c] = ll;
    *(ushort4*)&row[2048 + c] = hh;
}

__global__ void convB(const float* bq, const float* bk, const float* bv, float* o) {
    int t = threadIdx.x;
    const float* s = (blockIdx.x == 0) ? bq : (blockIdx.x == 1) ? bk : bv;
    o[blockIdx.x * 1024 + t] = s[t];
}

// ---------------------------------------------------------------------------
// mma.sync bf16 GEMM:  C[m,n] = sum_k A[m,k]*B[n,k] + bias[n]
// A: M x K3 bf16 row-major, B: N x K3 bf16 row-major (NT), C fp32 (ldc stride).
// 128x128 CTA tile, K-chunk 64, 4-stage cp.async, 8 warps (4x2), warp 32x64.
// ---------------------------------------------------------------------------
#define BM 128
#define BN 128
#define BKE 64                       // bf16 K elements per chunk (128B rows)
#define NCH (K3 / BKE)               // 48
#define NSTG 4
#define STG_A (BM * 128)             // 16384 B
#define STG_B (BN * 128)             // 16384 B
#define STGB  (STG_A + STG_B)        // 32768 B / stage
#define GEMM_SMEM (NSTG * STGB)      // 131072 B

__global__ void __launch_bounds__(256, 1)
gemm3(const __nv_bfloat16* __restrict__ A, const __nv_bfloat16* __restrict__ B,
      const float* __restrict__ bias, float* __restrict__ C, int ldc)
{
    extern __shared__ char smem[];
    const uint32_t sb = s2u(smem);
    const int tid  = threadIdx.x;
    const int w    = tid >> 5, lane = tid & 31;
    const int wm   = w >> 1;          // 0..3 (M)
    const int wn   = w & 1;           // 0..1 (N)
    const int row0 = blockIdx.y * BM, col0 = blockIdx.x * BN;

    const __nv_bfloat16* Abase = A + (size_t)row0 * K3;
    const __nv_bfloat16* Bbase = B + (size_t)col0 * K3;

    auto load_chunk = [&](int c, int s) {
        const uint32_t stg = sb + s * STGB;
#pragma unroll
        for (int r = 0; r < 8; r++) {
            int f   = tid + (r << 8);        // 0..2047 16B-chunk id
            int isB = f >> 10;               // A: 1024 chunks, B: 1024 chunks
            int fl  = f & 1023;
            int rr  = fl >> 3, seg = fl & 7;
            const __nv_bfloat16* g = (isB ? Bbase : Abase) + (size_t)rr * K3 + c * BKE + seg * 8;
            uint32_t d = stg + (isB ? STG_A : 0) + swz((uint32_t)(rr * 128 + seg * 16));
            asm volatile("cp.async.cg.shared.global [%0], [%1], 16;" :: "r"(d), "l"(g) : "memory");
        }
        asm volatile("cp.async.commit_group;" ::: "memory");
    };

    // prologue: 3 stages in flight
    load_chunk(0, 0); load_chunk(1, 1); load_chunk(2, 2);

    float acc[2][8][4];
#pragma unroll
    for (int i = 0; i < 2; i++)
#pragma unroll
        for (int j = 0; j < 8; j++)
#pragma unroll
            for (int k = 0; k < 4; k++) acc[i][j][k] = 0.0f;

    // ldmatrix address pattern (same for A and B tiles):
    // row = tileBase + (lane&15), byteoff = kk*32 + (lane>>4)*16
    const int lr = lane & 15;
    const int lc = (lane >> 4) * 16;

#pragma unroll 1
    for (int c = 0; c < NCH; c++) {
        if (c < NCH - 2)       asm volatile("cp.async.wait_group 2;" ::: "memory");
        else if (c == NCH - 2) asm volatile("cp.async.wait_group 1;" ::: "memory");
        else                   asm volatile("cp.async.wait_group 0;" ::: "memory");
        __syncthreads();

        const uint32_t sa  = sb + (c & 3) * STGB;
        const uint32_t sbb = sa + STG_A;

#pragma unroll
        for (int kk = 0; kk < 4; kk++) {
            uint32_t Ar[2][4], Br[4][4];
#pragma unroll
            for (int tm = 0; tm < 2; tm++) {
                int row = wm * 32 + tm * 16 + lr;
                ldsm4(Ar[tm], sa + swz((uint32_t)(row * 128 + kk * 32 + lc)));
            }
#pragma unroll
            for (int tb = 0; tb < 4; tb++) {
                int row = wn * 64 + tb * 16 + lr;
                ldsm4(Br[tb], sbb + swz((uint32_t)(row * 128 + kk * 32 + lc)));
            }
#pragma unroll
            for (int tm = 0; tm < 2; tm++)
#pragma unroll
                for (int tn = 0; tn < 8; tn++) {
                    int tb = tn >> 1, h = tn & 1;
                    mma16816(acc[tm][tn], Ar[tm], Br[tb][h], Br[tb][h + 2]);
                }
        }

        if (c + 3 < NCH) load_chunk(c + 3, (c + 3) & 3);
    }

    // ---------------- epilogue: bias add + direct fp32 stores -------------
#pragma unroll
    for (int tm = 0; tm < 2; tm++) {
        int r0 = row0 + wm * 32 + tm * 16 + (lane >> 2);
#pragma unroll
        for (int tn = 0; tn < 8; tn++) {
            int cc = col0 + wn * 64 + tn * 8 + ((lane & 3) << 1);
            float2 bv = *(const float2*)&bias[cc];
            float2 o0, o1;
            o0.x = acc[tm][tn][0] + bv.x; o0.y = acc[tm][tn][1] + bv.y;
            o1.x = acc[tm][tn][2] + bv.x; o1.y = acc[tm][tn][3] + bv.y;
            *(float2*)&C[(size_t)r0 * ldc + cc]       = o0;
            *(float2*)&C[(size_t)(r0 + 8) * ldc + cc] = o1;
        }
    }
}

// ---------------------------------------------------------------------------
// Per-token "attention" (head-mixing 16x16) — writes split-bf16 A operand
// ---------------------------------------------------------------------------
__global__ void __launch_bounds__(256)
attn_kernel(const float* __restrict__ QKV, __nv_bfloat16* __restrict__ Mout)
{
    const int token = blockIdx.x;
    const int n = token >> 13;
    const int s = token & 8191;
    const float* base = QKV + (size_t)token * 3072;

    __shared__ float qs[16 * 64];
    __shared__ float ks[64 * 17];
    __shared__ float vs[16 * 64];
    __shared__ float es[16 * 16];

    const int tid = threadIdx.x;

    {
        float4 fq = ((const float4*)base)[tid];
        ((float4*)qs)[tid] = fq;
        float4 fv = ((const float4*)(base + 2 * EMBED))[tid];
        ((float4*)vs)[tid] = fv;
        float4 fk = ((const float4*)(base + EMBED))[tid];
        int j  = tid >> 4;
        int d0 = (tid & 15) << 2;
        ks[(d0 + 0) * 17 + j] = fk.x;
        ks[(d0 + 1) * 17 + j] = fk.y;
        ks[(d0 + 2) * 17 + j] = fk.z;
        ks[(d0 + 3) * 17 + j] = fk.w;
    }
    __syncthreads();

    {
        const int i = tid >> 4, j = tid & 15;
        float sum = 0.0f;
#pragma unroll
        for (int d = 0; d < 64; d++)
            sum += qs[i * 64 + d] * ks[d * 17 + j];
        float val = sum * 0.03125f;    // 1/sqrt(1024)

        float mx = val;
#pragma unroll
        for (int off = 8; off > 0; off >>= 1)
            mx = fmaxf(mx, __shfl_xor_sync(0xffffffffu, mx, off, 16));
        float p = expf(val - mx);
        float z = p;
#pragma unroll
        for (int off = 8; off > 0; off >>= 1)
            z += __shfl_xor_sync(0xffffffffu, z, off, 16);
        es[i * 16 + j] = p / z;
    }
    __syncthreads();

    {
        const int i  = tid >> 4;
        const int d0 = (tid & 15) << 2;
        float4 o = make_float4(0.f, 0.f, 0.f, 0.f);
#pragma unroll
        for (int l = 0; l < 16; l++) {
            float a = es[i * 16 + l];
            float4 v = *(const float4*)&vs[l * 64 + d0];
            o.x += a * v.x; o.y += a * v.y; o.z += a * v.z; o.w += a * v.w;
        }
        const int row = n * SEQ + i * 512 + (s >> 4);
        const int col = (s & 15) * HDIM + d0;
        unsigned short h[4], l4[4];
        split2(o.x, h[0], l4[0]); split2(o.y, h[1], l4[1]);
        split2(o.z, h[2], l4[2]); split2(o.w, h[3], l4[3]);
        ushort4 hh = make_ushort4(h[0], h[1], h[2], h[3]);
        ushort4 ll = make_ushort4(l4[0], l4[1], l4[2], l4[3]);
        __nv_bfloat16* orow = Mout + (size_t)row * K3;
        *(ushort4*)&orow[col]        = hh;   // A layout: [hi|hi|lo]
        *(ushort4*)&orow[1024 + col] = hh;
        *(ushort4*)&orow[2048 + col] = ll;
    }
}

// ---------------------------------------------------------------------------
// Launch
// ---------------------------------------------------------------------------
extern "C" void kernel_launch(void* const* d_in, const int* in_sizes, int n_in,
                              void* d_out, int out_size)
{
    const float* x  = (const float*)d_in[0];
    const float* Wq = (const float*)d_in[1];
    const float* Wk = (const float*)d_in[2];
    const float* Wv = (const float*)d_in[3];
    const float* Wo = (const float*)d_in[4];
    const float* bq = (const float*)d_in[5];
    const float* bk = (const float*)d_in[6];
    const float* bv = (const float*)d_in[7];
    const float* bo = (const float*)d_in[8];
    float* out = (float*)d_out;

    __nv_bfloat16 *x3, *w3qkv, *w3o, *mid3;
    float *bqkv, *qkvf;
    cudaGetSymbolAddress((void**)&x3,    g_x3);
    cudaGetSymbolAddress((void**)&w3qkv, g_w3qkv);
    cudaGetSymbolAddress((void**)&w3o,   g_w3o);
    cudaGetSymbolAddress((void**)&bqkv,  g_bqkv);
    cudaGetSymbolAddress((void**)&qkvf,  g_qkv);
    cudaGetSymbolAddress((void**)&mid3,  g_mid3);

    cudaFuncSetAttribute(gemm3, cudaFuncAttributeMaxDynamicSharedMemorySize, GEMM_SMEM);

    convA<<<TOKENS, 256>>>(x, x3);
    convW<<<4096, 256>>>(Wq, Wk, Wv, Wo, w3qkv, w3o);
    convB<<<3, 1024>>>(bq, bk, bv, bqkv);

    // fused Q|K|V projection: [32768 x 3072] = x3 @ w3qkv^T + bqkv
    gemm3<<<dim3(3072 / BN, TOKENS / BM), 256, GEMM_SMEM>>>(x3, w3qkv, bqkv, qkvf, 3072);

    // head-mixing attention + gather, writes split-bf16 mid
    attn_kernel<<<TOKENS, 256>>>(qkvf, mid3);

    // output projection: out = mid @ Wo^T + bo
    gemm3<<<dim3(1024 / BN, TOKENS / BM), 256, GEMM_SMEM>>>(mid3, w3o, bo, out, 1024);
}

// round 12
// speedup vs baseline: 2.7352x; 1.1449x over previous
#include <cuda_runtime.h>
#include <cuda_bf16.h>
#include <stdint.h>
#include <math.h>

// ---------------------------------------------------------------------------
// Problem constants
// ---------------------------------------------------------------------------
#define EMBED 1024
#define K3    3072           // tripled K for 3xBF16 split GEMM
#define NB    4
#define SEQ   8192
#define TOKENS (NB * SEQ)    // 32768
#define HDIM  64

// ---------------------------------------------------------------------------
// Scratch (__device__ globals; alloc-free rule)
// ---------------------------------------------------------------------------
__device__ __nv_bfloat16 g_x3[(size_t)TOKENS * K3];    // x split  [hi|hi|lo]
__device__ __nv_bfloat16 g_w3qkv[(size_t)3072 * K3];   // Wq/Wk/Wv [hi|lo|hi]
__device__ __nv_bfloat16 g_w3o[(size_t)1024 * K3];     // Wo       [hi|lo|hi]
__device__ float         g_bqkv[3072];                 // concat(bq,bk,bv)
__device__ float         g_qkv[(size_t)TOKENS * 3072]; // fp32 Q|K|V per token
__device__ __nv_bfloat16 g_mid3[(size_t)TOKENS * K3];  // attn out [hi|hi|lo]

// ---------------------------------------------------------------------------
// Helpers
// ---------------------------------------------------------------------------
__device__ __forceinline__ unsigned short bfraw(__nv_bfloat16 h) {
    return *reinterpret_cast<unsigned short*>(&h);
}
__device__ __forceinline__ void split2(float v, unsigned short& h, unsigned short& l) {
    __nv_bfloat16 hb = __float2bfloat16(v);
    __nv_bfloat16 lb = __float2bfloat16(v - __bfloat162float(hb));
    h = bfraw(hb); l = bfraw(lb);
}
__device__ __forceinline__ uint32_t s2u(const void* p) {
    uint32_t a;
    asm("{ .reg .u64 t; cvta.to.shared.u64 t, %1; cvt.u32.u64 %0, t; }" : "=r"(a) : "l"(p));
    return a;
}
__device__ __forceinline__ uint32_t swz(uint32_t o) { return o ^ ((o >> 3) & 0x70); }

__device__ __forceinline__ void ldsm4(uint32_t* r, uint32_t addr) {
    asm volatile("ldmatrix.sync.aligned.m8n8.x4.shared.b16 {%0,%1,%2,%3}, [%4];"
                 : "=r"(r[0]), "=r"(r[1]), "=r"(r[2]), "=r"(r[3]) : "r"(addr));
}
__device__ __forceinline__ void mma16816(float* d, const uint32_t* a,
                                         uint32_t b0, uint32_t b1) {
    asm volatile(
        "mma.sync.aligned.m16n8k16.row.col.f32.bf16.bf16.f32 "
        "{%0,%1,%2,%3}, {%4,%5,%6,%7}, {%8,%9}, {%0,%1,%2,%3};"
        : "+f"(d[0]), "+f"(d[1]), "+f"(d[2]), "+f"(d[3])
        : "r"(a[0]), "r"(a[1]), "r"(a[2]), "r"(a[3]), "r"(b0), "r"(b1));
}

// ---------------------------------------------------------------------------
// Conversion kernels
// ---------------------------------------------------------------------------
__global__ void __launch_bounds__(256)
convA(const float* __restrict__ X, __nv_bfloat16* __restrict__ O) {
    int r = blockIdx.x;
    int c = threadIdx.x * 4;
    float4 v = *(const float4*)&X[(size_t)r * EMBED + c];
    unsigned short h[4], l[4];
    split2(v.x, h[0], l[0]); split2(v.y, h[1], l[1]);
    split2(v.z, h[2], l[2]); split2(v.w, h[3], l[3]);
    ushort4 hh = make_ushort4(h[0], h[1], h[2], h[3]);
    ushort4 ll = make_ushort4(l[0], l[1], l[2], l[3]);
    __nv_bfloat16* row = O + (size_t)r * K3;
    *(ushort4*)&row[c]        = hh;   // A layout: [hi|hi|lo]
    *(ushort4*)&row[1024 + c] = hh;
    *(ushort4*)&row[2048 + c] = ll;
}

__global__ void __launch_bounds__(256)
convW(const float* __restrict__ Wq, const float* __restrict__ Wk,
      const float* __restrict__ Wv, const float* __restrict__ Wo,
      __nv_bfloat16* __restrict__ wqkv, __nv_bfloat16* __restrict__ wo) {
    int r = blockIdx.x;              // 0..4095
    int c = threadIdx.x * 4;
    const float* src = (r < 1024) ? Wq : (r < 2048) ? Wk : (r < 3072) ? Wv : Wo;
    int sr = r & 1023;
    float4 v = *(const float4*)&src[(size_t)sr * EMBED + c];
    unsigned short h[4], l[4];
    split2(v.x, h[0], l[0]); split2(v.y, h[1], l[1]);
    split2(v.z, h[2], l[2]); split2(v.w, h[3], l[3]);
    ushort4 hh = make_ushort4(h[0], h[1], h[2], h[3]);
    ushort4 ll = make_ushort4(l[0], l[1], l[2], l[3]);
    __nv_bfloat16* row = (r < 3072) ? (wqkv + (size_t)r * K3)
                                    : (wo + (size_t)(r - 3072) * K3);
    *(ushort4*)&row[c]        = hh;   // B layout: [hi|lo|hi]
    *(ushort4*)&row[1024 + c] = ll;
    *(ushort4*)&row[2048 + c] = hh;
}

__global__ void convB(const float* bq, const float* bk, const float* bv, float* o) {
    int t = threadIdx.x;
    const float* s = (blockIdx.x == 0) ? bq : (blockIdx.x == 1) ? bk : bv;
    o[blockIdx.x * 1024 + t] = s[t];
}

// ---------------------------------------------------------------------------
// mma.sync bf16 GEMM:  C[m,n] = sum_k A[m,k]*B[n,k] + bias[n]
// A: M x K3 bf16 row-major, B: N x K3 bf16 row-major (NT), C fp32 (ldc stride).
// 128x128 CTA tile, K-chunk 64, 3-stage cp.async, 8 warps (4x2), warp 32x64.
// 2 CTAs/SM: 96KB smem/CTA, regs capped at 128 via __launch_bounds__(256,2).
// ---------------------------------------------------------------------------
#define BM 128
#define BN 128
#define BKE 64                       // bf16 K elements per chunk (128B rows)
#define NCH (K3 / BKE)               // 48
#define NSTG 3
#define STG_A (BM * 128)             // 16384 B
#define STG_B (BN * 128)             // 16384 B
#define STGB  (STG_A + STG_B)        // 32768 B / stage
#define GEMM_SMEM (NSTG * STGB)      // 98304 B

__global__ void __launch_bounds__(256, 2)
gemm3(const __nv_bfloat16* __restrict__ A, const __nv_bfloat16* __restrict__ B,
      const float* __restrict__ bias, float* __restrict__ C, int ldc)
{
    extern __shared__ char smem[];
    const uint32_t sb = s2u(smem);
    const int tid  = threadIdx.x;
    const int w    = tid >> 5, lane = tid & 31;
    const int wm   = w >> 1;          // 0..3 (M)
    const int wn   = w & 1;           // 0..1 (N)
    const int row0 = blockIdx.y * BM, col0 = blockIdx.x * BN;

    const __nv_bfloat16* Abase = A + (size_t)row0 * K3;
    const __nv_bfloat16* Bbase = B + (size_t)col0 * K3;

    auto load_chunk = [&](int c, int s) {
        const uint32_t stg = sb + s * STGB;
#pragma unroll
        for (int r = 0; r < 8; r++) {
            int f   = tid + (r << 8);        // 0..2047 16B-chunk id
            int isB = f >> 10;               // A: 1024 chunks, B: 1024 chunks
            int fl  = f & 1023;
            int rr  = fl >> 3, seg = fl & 7;
            const __nv_bfloat16* g = (isB ? Bbase : Abase) + (size_t)rr * K3 + c * BKE + seg * 8;
            uint32_t d = stg + (isB ? STG_A : 0) + swz((uint32_t)(rr * 128 + seg * 16));
            asm volatile("cp.async.cg.shared.global [%0], [%1], 16;" :: "r"(d), "l"(g) : "memory");
        }
        asm volatile("cp.async.commit_group;" ::: "memory");
    };

    // prologue: 2 stages in flight
    load_chunk(0, 0); load_chunk(1, 1);

    float acc[2][8][4];
#pragma unroll
    for (int i = 0; i < 2; i++)
#pragma unroll
        for (int j = 0; j < 8; j++)
#pragma unroll
            for (int k = 0; k < 4; k++) acc[i][j][k] = 0.0f;

    // ldmatrix address pattern (same for A and B tiles):
    // row = tileBase + (lane&15), byteoff = kk*32 + (lane>>4)*16
    const int lr = lane & 15;
    const int lc = (lane >> 4) * 16;

    int scur = 0, snext = 2;                 // stage of chunk c; stage for c+2
#pragma unroll 1
    for (int c = 0; c < NCH; c++) {
        if (c < NCH - 1) asm volatile("cp.async.wait_group 1;" ::: "memory");
        else             asm volatile("cp.async.wait_group 0;" ::: "memory");
        __syncthreads();

        // prefetch chunk c+2 into the stage vacated by chunk c-1
        // (all warps passed this iteration's barrier => done with c-1)
        if (c + 2 < NCH) load_chunk(c + 2, snext);

        const uint32_t sa  = sb + scur * STGB;
        const uint32_t sbb = sa + STG_A;

#pragma unroll
        for (int kk = 0; kk < 4; kk++) {
            uint32_t Ar[2][4], Br[4][4];
#pragma unroll
            for (int tm = 0; tm < 2; tm++) {
                int row = wm * 32 + tm * 16 + lr;
                ldsm4(Ar[tm], sa + swz((uint32_t)(row * 128 + kk * 32 + lc)));
            }
#pragma unroll
            for (int tb = 0; tb < 4; tb++) {
                int row = wn * 64 + tb * 16 + lr;
                ldsm4(Br[tb], sbb + swz((uint32_t)(row * 128 + kk * 32 + lc)));
            }
#pragma unroll
            for (int tm = 0; tm < 2; tm++)
#pragma unroll
                for (int tn = 0; tn < 8; tn++) {
                    int tb = tn >> 1, h = tn & 1;
                    mma16816(acc[tm][tn], Ar[tm], Br[tb][h], Br[tb][h + 2]);
                }
        }

        scur  = (scur == 2)  ? 0 : scur + 1;
        snext = (snext == 2) ? 0 : snext + 1;
    }

    // ---------------- epilogue: bias add + direct fp32 stores -------------
#pragma unroll
    for (int tm = 0; tm < 2; tm++) {
        int r0 = row0 + wm * 32 + tm * 16 + (lane >> 2);
#pragma unroll
        for (int tn = 0; tn < 8; tn++) {
            int cc = col0 + wn * 64 + tn * 8 + ((lane & 3) << 1);
            float2 bv = *(const float2*)&bias[cc];
            float2 o0, o1;
            o0.x = acc[tm][tn][0] + bv.x; o0.y = acc[tm][tn][1] + bv.y;
            o1.x = acc[tm][tn][2] + bv.x; o1.y = acc[tm][tn][3] + bv.y;
            *(float2*)&C[(size_t)r0 * ldc + cc]       = o0;
            *(float2*)&C[(size_t)(r0 + 8) * ldc + cc] = o1;
        }
    }
}

// ---------------------------------------------------------------------------
// Per-token "attention" (head-mixing 16x16) — writes split-bf16 A operand
// ---------------------------------------------------------------------------
__global__ void __launch_bounds__(256)
attn_kernel(const float* __restrict__ QKV, __nv_bfloat16* __restrict__ Mout)
{
    const int token = blockIdx.x;
    const int n = token >> 13;
    const int s = token & 8191;
    const float* base = QKV + (size_t)token * 3072;

    __shared__ float qs[16 * 64];
    __shared__ float ks[64 * 17];
    __shared__ float vs[16 * 64];
    __shared__ float es[16 * 16];

    const int tid = threadIdx.x;

    {
        float4 fq = ((const float4*)base)[tid];
        ((float4*)qs)[tid] = fq;
        float4 fv = ((const float4*)(base + 2 * EMBED))[tid];
        ((float4*)vs)[tid] = fv;
        float4 fk = ((const float4*)(base + EMBED))[tid];
        int j  = tid >> 4;
        int d0 = (tid & 15) << 2;
        ks[(d0 + 0) * 17 + j] = fk.x;
        ks[(d0 + 1) * 17 + j] = fk.y;
        ks[(d0 + 2) * 17 + j] = fk.z;
        ks[(d0 + 3) * 17 + j] = fk.w;
    }
    __syncthreads();

    {
        const int i = tid >> 4, j = tid & 15;
        float sum = 0.0f;
#pragma unroll
        for (int d = 0; d < 64; d++)
            sum += qs[i * 64 + d] * ks[d * 17 + j];
        float val = sum * 0.03125f;    // 1/sqrt(1024)

        float mx = val;
#pragma unroll
        for (int off = 8; off > 0; off >>= 1)
            mx = fmaxf(mx, __shfl_xor_sync(0xffffffffu, mx, off, 16));
        float p = expf(val - mx);
        float z = p;
#pragma unroll
        for (int off = 8; off > 0; off >>= 1)
            z += __shfl_xor_sync(0xffffffffu, z, off, 16);
        es[i * 16 + j] = p / z;
    }
    __syncthreads();

    {
        const int i  = tid >> 4;
        const int d0 = (tid & 15) << 2;
        float4 o = make_float4(0.f, 0.f, 0.f, 0.f);
#pragma unroll
        for (int l = 0; l < 16; l++) {
            float a = es[i * 16 + l];
            float4 v = *(const float4*)&vs[l * 64 + d0];
            o.x += a * v.x; o.y += a * v.y; o.z += a * v.z; o.w += a * v.w;
        }
        const int row = n * SEQ + i * 512 + (s >> 4);
        const int col = (s & 15) * HDIM + d0;
        unsigned short h[4], l4[4];
        split2(o.x, h[0], l4[0]); split2(o.y, h[1], l4[1]);
        split2(o.z, h[2], l4[2]); split2(o.w, h[3], l4[3]);
        ushort4 hh = make_ushort4(h[0], h[1], h[2], h[3]);
        ushort4 ll = make_ushort4(l4[0], l4[1], l4[2], l4[3]);
        __nv_bfloat16* orow = Mout + (size_t)row * K3;
        *(ushort4*)&orow[col]        = hh;   // A layout: [hi|hi|lo]
        *(ushort4*)&orow[1024 + col] = hh;
        *(ushort4*)&orow[2048 + col] = ll;
    }
}

// ---------------------------------------------------------------------------
// Launch
// ---------------------------------------------------------------------------
extern "C" void kernel_launch(void* const* d_in, const int* in_sizes, int n_in,
                              void* d_out, int out_size)
{
    const float* x  = (const float*)d_in[0];
    const float* Wq = (const float*)d_in[1];
    const float* Wk = (const float*)d_in[2];
    const float* Wv = (const float*)d_in[3];
    const float* Wo = (const float*)d_in[4];
    const float* bq = (const float*)d_in[5];
    const float* bk = (const float*)d_in[6];
    const float* bv = (const float*)d_in[7];
    const float* bo = (const float*)d_in[8];
    float* out = (float*)d_out;

    __nv_bfloat16 *x3, *w3qkv, *w3o, *mid3;
    float *bqkv, *qkvf;
    cudaGetSymbolAddress((void**)&x3,    g_x3);
    cudaGetSymbolAddress((void**)&w3qkv, g_w3qkv);
    cudaGetSymbolAddress((void**)&w3o,   g_w3o);
    cudaGetSymbolAddress((void**)&bqkv,  g_bqkv);
    cudaGetSymbolAddress((void**)&qkvf,  g_qkv);
    cudaGetSymbolAddress((void**)&mid3,  g_mid3);

    cudaFuncSetAttribute(gemm3, cudaFuncAttributeMaxDynamicSharedMemorySize, GEMM_SMEM);

    convA<<<TOKENS, 256>>>(x, x3);
    convW<<<4096, 256>>>(Wq, Wk, Wv, Wo, w3qkv, w3o);
    convB<<<3, 1024>>>(bq, bk, bv, bqkv);

    // fused Q|K|V projection: [32768 x 3072] = x3 @ w3qkv^T + bqkv
    gemm3<<<dim3(3072 / BN, TOKENS / BM), 256, GEMM_SMEM>>>(x3, w3qkv, bqkv, qkvf, 3072);

    // head-mixing attention + gather, writes split-bf16 mid
    attn_kernel<<<TOKENS, 256>>>(qkvf, mid3);

    // output projection: out = mid @ Wo^T + bo
    gemm3<<<dim3(1024 / BN, TOKENS / BM), 256, GEMM_SMEM>>>(mid3, w3o, bo, out, 1024);
}